// round 1
// baseline (speedup 1.0000x reference)
#include <cuda_runtime.h>
#include <cuda_bf16.h>
#include <cstddef>

// ---------------------------------------------------------------------------
// Windowed multi-head attention:
//   x[2,64,64,8,512] -> qkv = x @ w_qkv[512,1536]
//   per (window, head): dots = (q k^T) * scale * mask; softmax; out = attn @ v
//   y = attn_out @ w_out[512,512] + b_out
//
// Fixed shapes:
constexpr int M_TOTAL = 2 * 64 * 64 * 8;   // 65536 rows
constexpr int DIM     = 512;               // input dim / inner
constexpr int N_QKV   = 3 * 512;           // 1536
constexpr int HEADS   = 8;
constexpr int DHEAD   = 64;
constexpr int NTOK    = 8;                 // tokens per window
constexpr int N_WIN   = 2 * 64 * 64;       // 8192 windows
constexpr float SCALE = 0.125f;            // 64^-0.5
// ---------------------------------------------------------------------------

// Scratch (device globals: allocation-free per harness rules)
__device__ float g_qkv[(size_t)M_TOTAL * N_QKV];   // 402 MB
__device__ float g_attn[(size_t)M_TOTAL * DIM];    // 134 MB

// ---------------------------------------------------------------------------
// Tiled SGEMM: C[M,N] = A[M,K] @ B[K,N] (+ bias[N])
// BM=BN=128, BK=8, 256 threads, 8x8 register tile per thread.
// All dims divisible by tile sizes for this problem (65536, 1536/512, 512).
// ---------------------------------------------------------------------------
#define BM 128
#define BN 128
#define BK 8
#define TM 8
#define TN 8

__device__ __forceinline__ void sgemm_body(const float* __restrict__ A,
                                           const float* __restrict__ B,
                                           float*       __restrict__ C,
                                           const float* __restrict__ bias,
                                           int M, int N, int K)
{
    __shared__ float As[BK][BM];   // A stored transposed: As[k][m]
    __shared__ float Bs[BK][BN];

    const int tid  = threadIdx.x;        // 0..255
    const int cRow = blockIdx.y;         // M tile index
    const int cCol = blockIdx.x;         // N tile index

    A += (size_t)cRow * BM * K;
    B += (size_t)cCol * BN;
    C += (size_t)cRow * BM * N + (size_t)cCol * BN;

    // A tile load: 128x8 floats = 256 float4's, one per thread
    const int aRow = tid >> 1;                  // 0..127
    const int aCol = (tid & 1) * 4;             // 0 or 4
    // B tile load: 8x128 floats = 256 float4's
    const int bRow = tid >> 5;                  // 0..7
    const int bCol = (tid & 31) * 4;            // 0..124

    const int tRow = (tid >> 4) * TM;           // 0..120
    const int tCol = (tid & 15) * TN;           // 0..120

    float acc[TM][TN] = {};
    float regM[TM], regN[TN];

    for (int k0 = 0; k0 < K; k0 += BK) {
        float4 av = *reinterpret_cast<const float4*>(A + (size_t)aRow * K + aCol);
        As[aCol + 0][aRow] = av.x;
        As[aCol + 1][aRow] = av.y;
        As[aCol + 2][aRow] = av.z;
        As[aCol + 3][aRow] = av.w;
        float4 bv = *reinterpret_cast<const float4*>(B + (size_t)bRow * N + bCol);
        *reinterpret_cast<float4*>(&Bs[bRow][bCol]) = bv;
        __syncthreads();
        A += BK;
        B += (size_t)BK * N;

#pragma unroll
        for (int k = 0; k < BK; ++k) {
            // vectorized smem reads (aligned: tRow/tCol multiples of 8)
            float4 m0 = *reinterpret_cast<const float4*>(&As[k][tRow]);
            float4 m1 = *reinterpret_cast<const float4*>(&As[k][tRow + 4]);
            float4 n0 = *reinterpret_cast<const float4*>(&Bs[k][tCol]);
            float4 n1 = *reinterpret_cast<const float4*>(&Bs[k][tCol + 4]);
            regM[0]=m0.x; regM[1]=m0.y; regM[2]=m0.z; regM[3]=m0.w;
            regM[4]=m1.x; regM[5]=m1.y; regM[6]=m1.z; regM[7]=m1.w;
            regN[0]=n0.x; regN[1]=n0.y; regN[2]=n0.z; regN[3]=n0.w;
            regN[4]=n1.x; regN[5]=n1.y; regN[6]=n1.z; regN[7]=n1.w;
#pragma unroll
            for (int i = 0; i < TM; ++i)
#pragma unroll
                for (int j = 0; j < TN; ++j)
                    acc[i][j] = fmaf(regM[i], regN[j], acc[i][j]);
        }
        __syncthreads();
    }

#pragma unroll
    for (int i = 0; i < TM; ++i) {
#pragma unroll
        for (int j = 0; j < TN; j += 4) {
            float4 v = make_float4(acc[i][j], acc[i][j + 1], acc[i][j + 2], acc[i][j + 3]);
            if (bias != nullptr) {
                const float* bp = bias + (size_t)cCol * BN + tCol + j;
                v.x += bp[0]; v.y += bp[1]; v.z += bp[2]; v.w += bp[3];
            }
            *reinterpret_cast<float4*>(C + (size_t)(tRow + i) * N + tCol + j) = v;
        }
    }
}

__global__ __launch_bounds__(256, 2)
void gemm_qkv_kernel(const float* __restrict__ x, const float* __restrict__ w_qkv)
{
    sgemm_body(x, w_qkv, g_qkv, nullptr, M_TOTAL, N_QKV, DIM);
}

__global__ __launch_bounds__(256, 2)
void gemm_out_kernel(const float* __restrict__ w_out, const float* __restrict__ b_out,
                     float* __restrict__ out)
{
    sgemm_body(g_attn, w_out, out, b_out, M_TOTAL, DIM, DIM);
}

// ---------------------------------------------------------------------------
// Per (window, head) attention. Block = 64 threads (one per d in head dim).
// grid.x = N_WIN * HEADS = 65536.
// ---------------------------------------------------------------------------
__global__ __launch_bounds__(64)
void attn_kernel(const float* __restrict__ mask)
{
    __shared__ float qs[NTOK][DHEAD + 1];
    __shared__ float ks[NTOK][DHEAD + 1];
    __shared__ float vs[NTOK][DHEAD + 1];
    __shared__ float att[NTOK][NTOK];

    const int w = blockIdx.x >> 3;   // window 0..8191
    const int h = blockIdx.x & 7;    // head
    const int d = threadIdx.x;       // 0..63

    const size_t base = (size_t)w * NTOK * N_QKV + (size_t)h * DHEAD + d;
    const float* qp = g_qkv + base;

#pragma unroll
    for (int i = 0; i < NTOK; ++i) {
        qs[i][d] = qp[(size_t)i * N_QKV];
        ks[i][d] = qp[(size_t)i * N_QKV + 512];
        vs[i][d] = qp[(size_t)i * N_QKV + 1024];
    }
    __syncthreads();

    // dots: thread t -> (i = t/8, j = t%8); dot over 64 dims
    {
        const int i = d >> 3, j = d & 7;
        float s = 0.f;
#pragma unroll
        for (int t = 0; t < DHEAD; ++t)
            s = fmaf(qs[i][t], ks[j][t], s);
        s = s * SCALE * mask[(size_t)w * (NTOK * NTOK) + i * NTOK + j];
        att[i][j] = s;
    }
    __syncthreads();

    // softmax per row (8 threads, one per row)
    if (d < NTOK) {
        float m = att[d][0];
#pragma unroll
        for (int j = 1; j < NTOK; ++j) m = fmaxf(m, att[d][j]);
        float sum = 0.f;
        float e[NTOK];
#pragma unroll
        for (int j = 0; j < NTOK; ++j) { e[j] = __expf(att[d][j] - m); sum += e[j]; }
        const float inv = 1.f / sum;
#pragma unroll
        for (int j = 0; j < NTOK; ++j) att[d][j] = e[j] * inv;
    }
    __syncthreads();

    // out[i][d] = sum_j att[i][j] * v[j][d]
    const size_t obase = (size_t)w * NTOK * DIM + (size_t)h * DHEAD + d;
#pragma unroll
    for (int i = 0; i < NTOK; ++i) {
        float acc = 0.f;
#pragma unroll
        for (int j = 0; j < NTOK; ++j)
            acc = fmaf(att[i][j], vs[j][d], acc);
        g_attn[obase + (size_t)i * DIM] = acc;
    }
}

// ---------------------------------------------------------------------------
// kernel_launch: x, mask, w_qkv, w_out, b_out (metadata order) -> out (float32)
// ---------------------------------------------------------------------------
extern "C" void kernel_launch(void* const* d_in, const int* in_sizes, int n_in,
                              void* d_out, int out_size)
{
    const float* x     = (const float*)d_in[0];
    const float* mask  = (const float*)d_in[1];
    const float* w_qkv = (const float*)d_in[2];
    const float* w_out = (const float*)d_in[3];
    const float* b_out = (const float*)d_in[4];
    float* out = (float*)d_out;

    (void)in_sizes; (void)n_in; (void)out_size;

    dim3 g1(N_QKV / BN, M_TOTAL / BM);   // (12, 512)
    gemm_qkv_kernel<<<g1, 256>>>(x, w_qkv);

    attn_kernel<<<N_WIN * HEADS, 64>>>(mask);

    dim3 g2(DIM / BN, M_TOTAL / BM);     // (4, 512)
    gemm_out_kernel<<<g2, 256>>>(w_out, b_out, out);
}

// round 4
// speedup vs baseline: 1.5351x; 1.5351x over previous
#include <cuda_runtime.h>
#include <cuda_bf16.h>
#include <mma.h>
#include <cstdint>
#include <cstddef>

using namespace nvcuda;

// ---------------------------------------------------------------------------
// Windowed multi-head attention (fixed shapes):
//   x[2,64,64,8,512] @ w_qkv[512,1536] -> qkv
//   per (window, head): dots = (q k^T)*scale*mask; softmax; out = attn @ v
//   y = attn_out @ w_out[512,512] + b_out
// ---------------------------------------------------------------------------
constexpr int M_TOTAL = 2 * 64 * 64 * 8;   // 65536
constexpr int DIM     = 512;
constexpr int N_QKV   = 3 * 512;           // 1536
constexpr int HEADS   = 8;
constexpr int DHEAD   = 64;
constexpr int NTOK    = 8;
constexpr int N_WIN   = 2 * 64 * 64;       // 8192
constexpr float SCALE = 0.125f;

// Scratch (device globals: allocation-free per harness rules)
__device__ float g_qkv[(size_t)M_TOTAL * N_QKV];   // 402 MB
__device__ float g_attn[(size_t)M_TOTAL * DIM];    // 134 MB
__device__ float g_bias_tile[16 * DIM];            // b_out replicated over 16 rows

// ---------------------------------------------------------------------------
// TF32 tensor-core GEMM via nvcuda::wmma (m16n16k8):
//   C[M,N] = A[M,K] @ B[K,N] (+ bias[N])
// BM=BN=128, BK=16, 256 threads (8 warps, 4x2), warp tile 32x64
// (2x4 wmma tiles), fp32 accumulate. All dims divisible by tiles here.
// ---------------------------------------------------------------------------
#define BM 128
#define BN 128
#define BKt 16
#define ASTRIDE 24    // 16 + 8 pad (multiple of 4 floats = 16B, wmma-legal ldm)
#define BSTRIDE 136   // 128 + 8 pad

__device__ __forceinline__ void tc_gemm_body(const float* __restrict__ A,
                                             const float* __restrict__ B,
                                             float*       __restrict__ C,
                                             bool use_bias,
                                             int M, int N, int K)
{
    __shared__ float As[BM * ASTRIDE];     // [row][k], tf32-valued floats
    __shared__ float Bs[BKt * BSTRIDE];    // [k][col], tf32-valued floats

    const int tid    = threadIdx.x;
    const int warpid = tid >> 5;
    const int warp_m = warpid & 3;    // 0..3 -> 32 rows each
    const int warp_n = warpid >> 2;   // 0..1 -> 64 cols each

    const int cRow = blockIdx.y;
    const int cCol = blockIdx.x;

    A += (size_t)cRow * BM * K;
    B += (size_t)cCol * BN;
    C += (size_t)cRow * BM * N + (size_t)cCol * BN;

    wmma::fragment<wmma::accumulator, 16, 16, 8, float> acc[2][4];
#pragma unroll
    for (int mt = 0; mt < 2; ++mt)
#pragma unroll
        for (int nt = 0; nt < 4; ++nt)
            wmma::fill_fragment(acc[mt][nt], 0.0f);

    // gmem load mapping: 2 float4 per thread for each of A,B per K-step.
    // A tile: 128 rows x 16 k : idx in [0,512): row = idx>>2, kq = (idx&3)*4
    // B tile: 16 k x 128 cols : idx in [0,512): krow = idx>>5, col = (idx&31)*4
    for (int k0 = 0; k0 < K; k0 += BKt) {
#pragma unroll
        for (int it = 0; it < 2; ++it) {
            int idx  = tid + it * 256;
            int arow = idx >> 2;
            int akq  = (idx & 3) * 4;
            float4 av = *reinterpret_cast<const float4*>(A + (size_t)arow * K + akq);
            float* as = &As[arow * ASTRIDE + akq];
            as[0] = wmma::__float_to_tf32(av.x);
            as[1] = wmma::__float_to_tf32(av.y);
            as[2] = wmma::__float_to_tf32(av.z);
            as[3] = wmma::__float_to_tf32(av.w);

            int brow = idx >> 5;
            int bcol = (idx & 31) * 4;
            float4 bv = *reinterpret_cast<const float4*>(B + (size_t)brow * N + bcol);
            float* bs = &Bs[brow * BSTRIDE + bcol];
            bs[0] = wmma::__float_to_tf32(bv.x);
            bs[1] = wmma::__float_to_tf32(bv.y);
            bs[2] = wmma::__float_to_tf32(bv.z);
            bs[3] = wmma::__float_to_tf32(bv.w);
        }
        __syncthreads();
        A += BKt;
        B += (size_t)BKt * N;

#pragma unroll
        for (int ks = 0; ks < BKt; ks += 8) {
            wmma::fragment<wmma::matrix_a, 16, 16, 8, wmma::precision::tf32, wmma::row_major> af[2];
            wmma::fragment<wmma::matrix_b, 16, 16, 8, wmma::precision::tf32, wmma::row_major> bf[4];
#pragma unroll
            for (int mt = 0; mt < 2; ++mt)
                wmma::load_matrix_sync(af[mt], &As[(warp_m * 32 + mt * 16) * ASTRIDE + ks], ASTRIDE);
#pragma unroll
            for (int nt = 0; nt < 4; ++nt)
                wmma::load_matrix_sync(bf[nt], &Bs[ks * BSTRIDE + warp_n * 64 + nt * 16], BSTRIDE);
#pragma unroll
            for (int mt = 0; mt < 2; ++mt)
#pragma unroll
                for (int nt = 0; nt < 4; ++nt)
                    wmma::mma_sync(acc[mt][nt], af[mt], bf[nt], acc[mt][nt]);
        }
        __syncthreads();
    }

    // Epilogue: optional bias via replicated bias tile (accumulator-fragment
    // elementwise add -> no layout assumptions), then direct gmem store.
#pragma unroll
    for (int mt = 0; mt < 2; ++mt) {
        int row0 = warp_m * 32 + mt * 16;
#pragma unroll
        for (int nt = 0; nt < 4; ++nt) {
            int col0 = warp_n * 64 + nt * 16;
            if (use_bias) {
                wmma::fragment<wmma::accumulator, 16, 16, 8, float> bfra;
                wmma::load_matrix_sync(bfra, g_bias_tile + (size_t)cCol * BN + col0,
                                       DIM, wmma::mem_row_major);
#pragma unroll
                for (int e = 0; e < bfra.num_elements; ++e)
                    acc[mt][nt].x[e] += bfra.x[e];
            }
            wmma::store_matrix_sync(C + (size_t)row0 * N + col0, acc[mt][nt],
                                    N, wmma::mem_row_major);
        }
    }
}

__global__ __launch_bounds__(256)
void gemm_qkv_kernel(const float* __restrict__ x, const float* __restrict__ w_qkv)
{
    tc_gemm_body(x, w_qkv, g_qkv, false, M_TOTAL, N_QKV, DIM);
}

__global__ __launch_bounds__(256)
void gemm_out_kernel(float* __restrict__ out)
{
    tc_gemm_body(g_attn, /*B=*/nullptr, out, true, M_TOTAL, DIM, DIM);
}

// gemm_out needs w_out as B; pass through a dedicated kernel arg instead.
__global__ __launch_bounds__(256)
void gemm_out_kernel2(const float* __restrict__ w_out, float* __restrict__ out)
{
    tc_gemm_body(g_attn, w_out, out, true, M_TOTAL, DIM, DIM);
}

// Fill g_bias_tile: 16 replicated rows of b_out
__global__ void fill_bias_kernel(const float* __restrict__ b_out)
{
    int i = blockIdx.x * blockDim.x + threadIdx.x;   // 0..16*DIM-1
    if (i < 16 * DIM) g_bias_tile[i] = b_out[i & (DIM - 1)];
}

// ---------------------------------------------------------------------------
// Per (window, head) attention. Block = 64 threads. grid = N_WIN*HEADS.
// ---------------------------------------------------------------------------
__global__ __launch_bounds__(64)
void attn_kernel(const float* __restrict__ mask)
{
    __shared__ float qs[NTOK][DHEAD + 1];
    __shared__ float ks[NTOK][DHEAD + 1];
    __shared__ float vs[NTOK][DHEAD + 1];
    __shared__ float att[NTOK][NTOK];

    const int w = blockIdx.x >> 3;
    const int h = blockIdx.x & 7;
    const int d = threadIdx.x;

    const size_t base = (size_t)w * NTOK * N_QKV + (size_t)h * DHEAD + d;
    const float* qp = g_qkv + base;

#pragma unroll
    for (int i = 0; i < NTOK; ++i) {
        qs[i][d] = qp[(size_t)i * N_QKV];
        ks[i][d] = qp[(size_t)i * N_QKV + 512];
        vs[i][d] = qp[(size_t)i * N_QKV + 1024];
    }
    __syncthreads();

    {
        const int i = d >> 3, j = d & 7;
        float s = 0.f;
#pragma unroll
        for (int t = 0; t < DHEAD; ++t)
            s = fmaf(qs[i][t], ks[j][t], s);
        s = s * SCALE * mask[(size_t)w * (NTOK * NTOK) + i * NTOK + j];
        att[i][j] = s;
    }
    __syncthreads();

    if (d < NTOK) {
        float m = att[d][0];
#pragma unroll
        for (int j = 1; j < NTOK; ++j) m = fmaxf(m, att[d][j]);
        float sum = 0.f;
        float e[NTOK];
#pragma unroll
        for (int j = 0; j < NTOK; ++j) { e[j] = __expf(att[d][j] - m); sum += e[j]; }
        const float inv = 1.f / sum;
#pragma unroll
        for (int j = 0; j < NTOK; ++j) att[d][j] = e[j] * inv;
    }
    __syncthreads();

    const size_t obase = (size_t)w * NTOK * DIM + (size_t)h * DHEAD + d;
#pragma unroll
    for (int i = 0; i < NTOK; ++i) {
        float acc = 0.f;
#pragma unroll
        for (int j = 0; j < NTOK; ++j)
            acc = fmaf(att[i][j], vs[j][d], acc);
        g_attn[obase + (size_t)i * DIM] = acc;
    }
}

// ---------------------------------------------------------------------------
extern "C" void kernel_launch(void* const* d_in, const int* in_sizes, int n_in,
                              void* d_out, int out_size)
{
    const float* x     = (const float*)d_in[0];
    const float* mask  = (const float*)d_in[1];
    const float* w_qkv = (const float*)d_in[2];
    const float* w_out = (const float*)d_in[3];
    const float* b_out = (const float*)d_in[4];
    float* out = (float*)d_out;

    (void)in_sizes; (void)n_in; (void)out_size;

    fill_bias_kernel<<<(16 * DIM + 255) / 256, 256>>>(b_out);

    dim3 g1(N_QKV / BN, M_TOTAL / BM);   // (12, 512)
    gemm_qkv_kernel<<<g1, 256>>>(x, w_qkv);

    attn_kernel<<<N_WIN * HEADS, 64>>>(mask);

    dim3 g2(DIM / BN, M_TOTAL / BM);     // (4, 512)
    gemm_out_kernel2<<<g2, 256>>>(w_out, out);
}

// round 5
// speedup vs baseline: 1.5644x; 1.0191x over previous
#include <cuda_runtime.h>
#include <cuda_bf16.h>
#include <cuda_pipeline.h>
#include <mma.h>
#include <cstdint>
#include <cstddef>

using namespace nvcuda;

// ---------------------------------------------------------------------------
// Windowed multi-head attention (fixed shapes):
//   x[2,64,64,8,512] @ w_qkv[512,1536] -> qkv
//   per (window, head): dots = (q k^T)*scale*mask; softmax; out = attn @ v
//   y = attn_out @ w_out[512,512] + b_out
// ---------------------------------------------------------------------------
constexpr int M_TOTAL = 2 * 64 * 64 * 8;   // 65536
constexpr int DIM     = 512;
constexpr int N_QKV   = 3 * 512;           // 1536
constexpr int HEADS   = 8;
constexpr int DHEAD   = 64;
constexpr int NTOK    = 8;
constexpr int N_WIN   = 2 * 64 * 64;       // 8192
constexpr float SCALE = 0.125f;

// Scratch (device globals: allocation-free per harness rules)
__device__ float g_qkv[(size_t)M_TOTAL * N_QKV];   // 402 MB
__device__ float g_attn[(size_t)M_TOTAL * DIM];    // 134 MB
__device__ float g_bias_tile[16 * DIM];            // b_out replicated over 16 rows

// ---------------------------------------------------------------------------
// TF32 tensor-core GEMM via nvcuda::wmma (m16n16k8) with 2-stage cp.async
// double-buffered pipeline. C[M,N] = A[M,K] @ B[K,N] (+ bias[N]).
// BM=BN=128, BK=16, 256 threads (8 warps, 4x2), warp tile 32x64.
// Raw fp32 staged in smem; tf32 rounding applied to fragment registers.
// ---------------------------------------------------------------------------
#define BM 128
#define BN 128
#define BKt 16
#define ASTRIDE 20    // 16 + 4 pad floats; row pitch 80B (16B-aligned)
#define BSTRIDE 136   // 128 + 8 pad floats; row pitch 544B (16B-aligned)

__device__ __forceinline__ void tc_gemm_body(const float* __restrict__ A,
                                             const float* __restrict__ B,
                                             float*       __restrict__ C,
                                             bool use_bias,
                                             int M, int N, int K)
{
    __shared__ float As[2][BM * ASTRIDE];     // raw fp32, double-buffered
    __shared__ float Bs[2][BKt * BSTRIDE];

    const int tid    = threadIdx.x;
    const int warpid = tid >> 5;
    const int warp_m = warpid & 3;    // 0..3 -> 32 rows each
    const int warp_n = warpid >> 2;   // 0..1 -> 64 cols each

    const int cRow = blockIdx.y;
    const int cCol = blockIdx.x;

    A += (size_t)cRow * BM * K;
    B += (size_t)cCol * BN;
    C += (size_t)cRow * BM * N + (size_t)cCol * BN;

    // cp.async chunk mapping (16B each, 2 chunks per thread per matrix):
    // A tile 128x16: chunk c: row=c>>2, kq=(c&3)*4
    // B tile 16x128: chunk c: krow=c>>5, col=(c&31)*4
    auto load_tile = [&](int stage, int t) {
        const float* Asrc = A + (size_t)t * BKt;
        const float* Bsrc = B + (size_t)t * BKt * N;
#pragma unroll
        for (int it = 0; it < 2; ++it) {
            int c = tid + it * 256;
            int arow = c >> 2, akq = (c & 3) * 4;
            __pipeline_memcpy_async(&As[stage][arow * ASTRIDE + akq],
                                    Asrc + (size_t)arow * K + akq, 16);
            int brow = c >> 5, bcol = (c & 31) * 4;
            __pipeline_memcpy_async(&Bs[stage][brow * BSTRIDE + bcol],
                                    Bsrc + (size_t)brow * N + bcol, 16);
        }
    };

    wmma::fragment<wmma::accumulator, 16, 16, 8, float> acc[2][4];
#pragma unroll
    for (int mt = 0; mt < 2; ++mt)
#pragma unroll
        for (int nt = 0; nt < 4; ++nt)
            wmma::fill_fragment(acc[mt][nt], 0.0f);

    const int NT = K / BKt;

    load_tile(0, 0);
    __pipeline_commit();

    for (int t = 0; t < NT; ++t) {
        const int buf = t & 1;
        if (t + 1 < NT) {
            load_tile(buf ^ 1, t + 1);
            __pipeline_commit();
            __pipeline_wait_prior(1);
        } else {
            __pipeline_wait_prior(0);
        }
        __syncthreads();

#pragma unroll
        for (int ks = 0; ks < BKt; ks += 8) {
            wmma::fragment<wmma::matrix_a, 16, 16, 8, wmma::precision::tf32, wmma::row_major> af[2];
            wmma::fragment<wmma::matrix_b, 16, 16, 8, wmma::precision::tf32, wmma::row_major> bf[4];
#pragma unroll
            for (int mt = 0; mt < 2; ++mt) {
                wmma::load_matrix_sync(af[mt], &As[buf][(warp_m * 32 + mt * 16) * ASTRIDE + ks], ASTRIDE);
#pragma unroll
                for (int e = 0; e < af[mt].num_elements; ++e)
                    af[mt].x[e] = wmma::__float_to_tf32(af[mt].x[e]);
            }
#pragma unroll
            for (int nt = 0; nt < 4; ++nt) {
                wmma::load_matrix_sync(bf[nt], &Bs[buf][ks * BSTRIDE + warp_n * 64 + nt * 16], BSTRIDE);
#pragma unroll
                for (int e = 0; e < bf[nt].num_elements; ++e)
                    bf[nt].x[e] = wmma::__float_to_tf32(bf[nt].x[e]);
            }
#pragma unroll
            for (int mt = 0; mt < 2; ++mt)
#pragma unroll
                for (int nt = 0; nt < 4; ++nt)
                    wmma::mma_sync(acc[mt][nt], af[mt], bf[nt], acc[mt][nt]);
        }
        __syncthreads();   // protect buf before next-next prefetch overwrites it
    }

    // Epilogue: optional bias via replicated bias tile, then direct gmem store.
#pragma unroll
    for (int mt = 0; mt < 2; ++mt) {
        int row0 = warp_m * 32 + mt * 16;
#pragma unroll
        for (int nt = 0; nt < 4; ++nt) {
            int col0 = warp_n * 64 + nt * 16;
            if (use_bias) {
                wmma::fragment<wmma::accumulator, 16, 16, 8, float> bfra;
                wmma::load_matrix_sync(bfra, g_bias_tile + (size_t)cCol * BN + col0,
                                       DIM, wmma::mem_row_major);
#pragma unroll
                for (int e = 0; e < bfra.num_elements; ++e)
                    acc[mt][nt].x[e] += bfra.x[e];
            }
            wmma::store_matrix_sync(C + (size_t)row0 * N + col0, acc[mt][nt],
                                    N, wmma::mem_row_major);
        }
    }
}

__global__ __launch_bounds__(256)
void gemm_qkv_kernel(const float* __restrict__ x, const float* __restrict__ w_qkv)
{
    tc_gemm_body(x, w_qkv, g_qkv, false, M_TOTAL, N_QKV, DIM);
}

__global__ __launch_bounds__(256)
void gemm_out_kernel2(const float* __restrict__ w_out, float* __restrict__ out)
{
    tc_gemm_body(g_attn, w_out, out, true, M_TOTAL, DIM, DIM);
}

// Fill g_bias_tile: 16 replicated rows of b_out
__global__ void fill_bias_kernel(const float* __restrict__ b_out)
{
    int i = blockIdx.x * blockDim.x + threadIdx.x;   // 0..16*DIM-1
    if (i < 16 * DIM) g_bias_tile[i] = b_out[i & (DIM - 1)];
}

// ---------------------------------------------------------------------------
// Per (window, head) attention. Block = 64 threads. grid = N_WIN*HEADS.
// ---------------------------------------------------------------------------
__global__ __launch_bounds__(64)
void attn_kernel(const float* __restrict__ mask)
{
    __shared__ float qs[NTOK][DHEAD + 1];
    __shared__ float ks[NTOK][DHEAD + 1];
    __shared__ float vs[NTOK][DHEAD + 1];
    __shared__ float att[NTOK][NTOK];

    const int w = blockIdx.x >> 3;
    const int h = blockIdx.x & 7;
    const int d = threadIdx.x;

    const size_t base = (size_t)w * NTOK * N_QKV + (size_t)h * DHEAD + d;
    const float* qp = g_qkv + base;

#pragma unroll
    for (int i = 0; i < NTOK; ++i) {
        qs[i][d] = qp[(size_t)i * N_QKV];
        ks[i][d] = qp[(size_t)i * N_QKV + 512];
        vs[i][d] = qp[(size_t)i * N_QKV + 1024];
    }
    __syncthreads();

    {
        const int i = d >> 3, j = d & 7;
        float s = 0.f;
#pragma unroll
        for (int t = 0; t < DHEAD; ++t)
            s = fmaf(qs[i][t], ks[j][t], s);
        s = s * SCALE * mask[(size_t)w * (NTOK * NTOK) + i * NTOK + j];
        att[i][j] = s;
    }
    __syncthreads();

    if (d < NTOK) {
        float m = att[d][0];
#pragma unroll
        for (int j = 1; j < NTOK; ++j) m = fmaxf(m, att[d][j]);
        float sum = 0.f;
        float e[NTOK];
#pragma unroll
        for (int j = 0; j < NTOK; ++j) { e[j] = __expf(att[d][j] - m); sum += e[j]; }
        const float inv = 1.f / sum;
#pragma unroll
        for (int j = 0; j < NTOK; ++j) att[d][j] = e[j] * inv;
    }
    __syncthreads();

    const size_t obase = (size_t)w * NTOK * DIM + (size_t)h * DHEAD + d;
#pragma unroll
    for (int i = 0; i < NTOK; ++i) {
        float acc = 0.f;
#pragma unroll
        for (int j = 0; j < NTOK; ++j)
            acc = fmaf(att[i][j], vs[j][d], acc);
        g_attn[obase + (size_t)i * DIM] = acc;
    }
}

// ---------------------------------------------------------------------------
extern "C" void kernel_launch(void* const* d_in, const int* in_sizes, int n_in,
                              void* d_out, int out_size)
{
    const float* x     = (const float*)d_in[0];
    const float* mask  = (const float*)d_in[1];
    const float* w_qkv = (const float*)d_in[2];
    const float* w_out = (const float*)d_in[3];
    const float* b_out = (const float*)d_in[4];
    float* out = (float*)d_out;

    (void)in_sizes; (void)n_in; (void)out_size;

    fill_bias_kernel<<<(16 * DIM + 255) / 256, 256>>>(b_out);

    dim3 g1(N_QKV / BN, M_TOTAL / BM);   // (12, 512)
    gemm_qkv_kernel<<<g1, 256>>>(x, w_qkv);

    attn_kernel<<<N_WIN * HEADS, 64>>>(mask);

    dim3 g2(DIM / BN, M_TOTAL / BM);     // (4, 512)
    gemm_out_kernel2<<<g2, 256>>>(w_out, out);
}